// round 6
// baseline (speedup 1.0000x reference)
#include <cuda_runtime.h>

// Problem constants
#define KI     9
#define KO     3
#define C_IN   3
#define H_IN   192
#define W_IN   192
#define B2     16               // B*L
#define HP     184              // H_IN - KI + 1
#define OUT_H  186
#define WIDTH  50
#define WP1    56               // layer-1/2 row padding (two 28-col halves)
#define HALF   28
#define WP3    12
#define IN_DIM 243
#define TILE_X 32               // 2 positions per thread (tx, tx+16)
#define TILE_Y 16
#define XTW    40               // TILE_X + KI - 1
#define XTH    24               // TILE_Y + KI - 1
#define XSTR   48               // padded input-tile row stride (floats)
#define GX     6
#define GY     12
#define NTHR   256

// Scratch: per-position MLP outputs, plane-major [o][b2][py][px]
__device__ float g_y[9 * B2 * HP * HP];

// ---- packed fp32x2 helpers (sm_100+) ----
__device__ __forceinline__ void fma2(unsigned long long& d,
                                     unsigned long long a,
                                     unsigned long long b) {
    asm("fma.rn.f32x2 %0, %1, %2, %0;" : "+l"(d) : "l"(a), "l"(b));
}
__device__ __forceinline__ unsigned long long pack2(float f) {
    unsigned long long r;
    asm("mov.b64 %0, {%1, %1};" : "=l"(r) : "f"(f));
    return r;
}
__device__ __forceinline__ float2 unpack2(unsigned long long v) {
    float2 r;
    asm("mov.b64 {%0, %1}, %2;" : "=f"(r.x), "=f"(r.y) : "l"(v));
    return r;
}

// Layers 2+3 for one position. Features come from the smem park (already
// relu'd floats at PARKP[k*NTHR]); only h2p (28 u64) is register-resident.
#define TAIL_LAYERS(PARKP, GYB, PLANE)                                        \
    do {                                                                      \
        unsigned long long h2p[28];                                           \
        {                                                                     \
            const ulonglong2* bb = (const ulonglong2*)sb2;                    \
            _Pragma("unroll")                                                 \
            for (int i = 0; i < 14; i++) {                                    \
                ulonglong2 v = bb[i];                                         \
                h2p[2*i] = v.x; h2p[2*i+1] = v.y;                             \
            }                                                                 \
        }                                                                     \
        _Pragma("unroll 2")                                                   \
        for (int k = 0; k < WIDTH; k++) {                                     \
            unsigned long long f = pack2((PARKP)[k * NTHR]);                  \
            const ulonglong2* w = (const ulonglong2*)(sW2 + k * WP1);         \
            _Pragma("unroll")                                                 \
            for (int i = 0; i < 14; i++) {                                    \
                ulonglong2 wv = w[i];                                         \
                fma2(h2p[2*i],   f, wv.x);                                    \
                fma2(h2p[2*i+1], f, wv.y);                                    \
            }                                                                 \
        }                                                                     \
        unsigned long long yp[6];                                             \
        {                                                                     \
            const ulonglong2* bb = (const ulonglong2*)sb3;                    \
            _Pragma("unroll")                                                 \
            for (int i = 0; i < 3; i++) {                                     \
                ulonglong2 v = bb[i];                                         \
                yp[2*i] = v.x; yp[2*i+1] = v.y;                               \
            }                                                                 \
        }                                                                     \
        _Pragma("unroll")                                                     \
        for (int k = 0; k < WIDTH; k += 2) {                                  \
            float2 p = unpack2(h2p[k >> 1]);                                  \
            {                                                                 \
                unsigned long long f = pack2(fmaxf(p.x, 0.f));                \
                const ulonglong2* w = (const ulonglong2*)(sW3 + k * WP3);     \
                _Pragma("unroll")                                             \
                for (int i = 0; i < 3; i++) {                                 \
                    ulonglong2 wv = w[i];                                     \
                    fma2(yp[2*i],   f, wv.x);                                 \
                    fma2(yp[2*i+1], f, wv.y);                                 \
                }                                                             \
            }                                                                 \
            {                                                                 \
                unsigned long long f = pack2(fmaxf(p.y, 0.f));                \
                const ulonglong2* w = (const ulonglong2*)(sW3 + (k+1)*WP3);   \
                _Pragma("unroll")                                             \
                for (int i = 0; i < 3; i++) {                                 \
                    ulonglong2 wv = w[i];                                     \
                    fma2(yp[2*i],   f, wv.x);                                 \
                    fma2(yp[2*i+1], f, wv.y);                                 \
                }                                                             \
            }                                                                 \
        }                                                                     \
        _Pragma("unroll")                                                     \
        for (int i = 0; i < 5; i++) {                                         \
            float2 p = unpack2(yp[i]);                                        \
            (GYB)[(2*i) * (PLANE)] = p.x;                                     \
            if (2*i + 1 < 9) (GYB)[(2*i + 1) * (PLANE)] = p.y;                \
        }                                                                     \
    } while (0)

__global__ __launch_bounds__(NTHR, 1) void mlp_kernel(
    const float* __restrict__ x,
    const float* __restrict__ W1, const float* __restrict__ b1,
    const float* __restrict__ W2, const float* __restrict__ b2,
    const float* __restrict__ W3, const float* __restrict__ b3)
{
    extern __shared__ float smem[];
    float* sW1  = smem;                      // [243][56]  W1^T, padded
    float* sW2  = sW1 + IN_DIM * WP1;        // [50][56]   W2^T, padded
    float* sW3  = sW2 + WIDTH * WP1;         // [50][12]   W3^T, padded
    float* sb1  = sW3 + WIDTH * WP3;         // [56]
    float* sb2  = sb1 + WP1;                 // [56]
    float* sb3  = sb2 + WP1;                 // [12]
    float* sx   = sb3 + WP3;                 // [3][24][48]
    float* park = sx + C_IN * XTH * XSTR;    // [2*50][256] relu'd h1, per-thread

    const int tid = threadIdx.x;

    for (int idx = tid; idx < WIDTH * IN_DIM; idx += NTHR) {
        int j = idx / IN_DIM, k = idx - j * IN_DIM;
        sW1[k * WP1 + j] = W1[idx];
    }
    for (int k = tid; k < IN_DIM; k += NTHR) {
        #pragma unroll
        for (int j = WIDTH; j < WP1; j++) sW1[k * WP1 + j] = 0.f;
    }
    for (int idx = tid; idx < WIDTH * WIDTH; idx += NTHR) {
        int j = idx / WIDTH, k = idx - j * WIDTH;
        sW2[k * WP1 + j] = W2[idx];
    }
    for (int k = tid; k < WIDTH; k += NTHR) {
        #pragma unroll
        for (int j = WIDTH; j < WP1; j++) sW2[k * WP1 + j] = 0.f;
    }
    for (int idx = tid; idx < 9 * WIDTH; idx += NTHR) {
        int o = idx / WIDTH, k = idx - o * WIDTH;
        sW3[k * WP3 + o] = W3[idx];
    }
    for (int k = tid; k < WIDTH; k += NTHR) {
        sW3[k * WP3 + 9] = 0.f; sW3[k * WP3 + 10] = 0.f; sW3[k * WP3 + 11] = 0.f;
    }
    if (tid < WP1) sb1[tid] = (tid < WIDTH) ? b1[tid] : 0.f;
    if (tid < WP1) sb2[tid] = (tid < WIDTH) ? b2[tid] : 0.f;
    if (tid < WP3) sb3[tid] = (tid < 9) ? b3[tid] : 0.f;

    const int b   = blockIdx.z;
    const int py0 = blockIdx.y * TILE_Y;
    const int px0 = blockIdx.x * TILE_X;
    const float* xb = x + (size_t)b * (C_IN * H_IN * W_IN);
    for (int idx = tid; idx < C_IN * XTH * XTW; idx += NTHR) {
        int c = idx / (XTH * XTW);
        int r = (idx / XTW) % XTH;
        int q = idx % XTW;
        int gy = py0 + r, gx = px0 + q;
        float v = 0.f;
        if (gy < H_IN && gx < W_IN) v = xb[(c * H_IN + gy) * W_IN + gx];
        sx[(c * XTH + r) * XSTR + q] = v;
    }
    __syncthreads();

    const int tx = tid & 15;
    const int ty = tid >> 4;
    const int py = py0 + ty;
    if (py >= HP) return;                    // no __syncthreads past this point
    const int pxA = px0 + tx;
    const int pxB = pxA + 16;

    float* parkA = park + tid;               // slots [k*NTHR]
    float* parkB = park + WIDTH * NTHR + tid;

    // ------- layer 1: two passes of 28 neurons, 2 positions per thread ----
    for (int h = 0; h < 2; h++) {
        unsigned long long aA[14], aB[14];
        {
            const ulonglong2* bb = (const ulonglong2*)(sb1 + h * HALF);
            #pragma unroll
            for (int i = 0; i < 7; i++) {
                ulonglong2 v = bb[i];
                aA[2*i] = v.x; aA[2*i+1] = v.y;
                aB[2*i] = v.x; aB[2*i+1] = v.y;
            }
        }
        const float* wrow = sW1 + h * HALF;
        for (int c = 0; c < C_IN; c++) {
            for (int di = 0; di < KI; di++) {
                const float* frow = sx + (c * XTH + ty + di) * XSTR + tx;
                #pragma unroll
                for (int dj = 0; dj < KI; dj++) {
                    unsigned long long fA = pack2(frow[dj]);
                    unsigned long long fB = pack2(frow[dj + 16]);
                    const ulonglong2* w = (const ulonglong2*)wrow;
                    #pragma unroll
                    for (int i = 0; i < 7; i++) {
                        ulonglong2 wv = w[i];
                        fma2(aA[2*i],   fA, wv.x);
                        fma2(aA[2*i+1], fA, wv.y);
                        fma2(aB[2*i],   fB, wv.x);
                        fma2(aB[2*i+1], fB, wv.y);
                    }
                    wrow += WP1;
                }
            }
        }
        // relu + park (floats, per-thread private slots)
        #pragma unroll
        for (int i = 0; i < 14; i++) {
            int j0 = h * HALF + 2 * i;
            float2 pA = unpack2(aA[i]);
            float2 pB = unpack2(aB[i]);
            if (j0 < WIDTH) {
                parkA[j0 * NTHR] = fmaxf(pA.x, 0.f);
                parkB[j0 * NTHR] = fmaxf(pB.x, 0.f);
            }
            if (j0 + 1 < WIDTH) {
                parkA[(j0 + 1) * NTHR] = fmaxf(pA.y, 0.f);
                parkB[(j0 + 1) * NTHR] = fmaxf(pB.y, 0.f);
            }
        }
    }

    // ------- layers 2+3, per position, features streamed from park -------
    const int prow = py * HP;
    const int plane = B2 * HP * HP;
    {
        float* gyA = g_y + (size_t)b * (HP * HP) + prow + pxA;
        TAIL_LAYERS(parkA, gyA, plane);
    }
    if (pxB < HP) {
        float* gyB = g_y + (size_t)b * (HP * HP) + prow + pxB;
        TAIL_LAYERS(parkB, gyB, plane);
    }
}

// Fold (overlap-add + divisor) as a pure gather: out[b][oi][oj]
__global__ __launch_bounds__(256) void fold_kernel(float* __restrict__ out)
{
    int idx = blockIdx.x * blockDim.x + threadIdx.x;
    const int total = B2 * OUT_H * OUT_H;
    if (idx >= total) return;
    int oj = idx % OUT_H;
    int t  = idx / OUT_H;
    int oi = t % OUT_H;
    int b  = t / OUT_H;

    float acc = 0.f;
    int cnt = 0;
    #pragma unroll
    for (int di = 0; di < KO; di++) {
        int pi = oi - di;
        if (pi < 0 || pi >= HP) continue;
        #pragma unroll
        for (int dj = 0; dj < KO; dj++) {
            int pj = oj - dj;
            if (pj < 0 || pj >= HP) continue;
            acc += g_y[((di * KO + dj) * B2 + b) * (HP * HP) + pi * HP + pj];
            cnt++;
        }
    }
    out[idx] = acc / (float)cnt;
}

extern "C" void kernel_launch(void* const* d_in, const int* in_sizes, int n_in,
                              void* d_out, int out_size)
{
    const float* x  = (const float*)d_in[0];
    const float* W1 = (const float*)d_in[1];
    const float* b1 = (const float*)d_in[2];
    const float* W2 = (const float*)d_in[3];
    const float* b2 = (const float*)d_in[4];
    const float* W3 = (const float*)d_in[5];
    const float* b3 = (const float*)d_in[6];
    float* out = (float*)d_out;

    const int smem_words = IN_DIM * WP1 + WIDTH * WP1 + WIDTH * WP3
                         + WP1 + WP1 + WP3 + C_IN * XTH * XSTR
                         + 2 * WIDTH * NTHR;
    const int smem_bytes = smem_words * 4;   // 184,752 B
    cudaFuncSetAttribute(mlp_kernel,
                         cudaFuncAttributeMaxDynamicSharedMemorySize, smem_bytes);

    dim3 grid(GX, GY, B2);
    mlp_kernel<<<grid, NTHR, smem_bytes>>>(x, W1, b1, W2, b2, W3, b3);

    const int total = B2 * OUT_H * OUT_H;
    fold_kernel<<<(total + 255) / 256, 256>>>(out);
}

// round 8
// speedup vs baseline: 1.3643x; 1.3643x over previous
#include <cuda_runtime.h>
#include <cstdint>

// ---------------- problem constants ----------------
#define KI     9
#define KO     3
#define C_IN   3
#define H_IN   192
#define W_IN   192
#define B2     16
#define HP     184            // H - KI + 1
#define OUT_H  186

// ---------------- tiling ----------------
#define TROWS  4
#define TCOLS  32
#define YG     46             // 184/4
#define XG     6              // ceil(184/32)
#define NTILES (B2*YG*XG)     // 4416
#define NTHR   256
#define NCTA   148

// GEMM dims (bias folded as constant-1 feature)
#define K1     256            // 243 real + bias@243 + pad
#define K2     64             // 50 real + bias@50 + pad
#define N12    64             // hidden padded (50 -> 64)
#define N3     16             // out padded (9 -> 16)

// input tile
#define SXH    12             // TROWS + 8
#define SXW    40             // TCOLS + 8

// smem strides (floats); 260%32==4, 68%32==4 -> conflict-free fragment loads
#define STRW1  260
#define STR    68

// ---------------- smem layout (float offsets) ----------------
#define W1_OFF 0              // [64][260] = 16640
#define W2_OFF 16640          // [64][68]  = 4352
#define W3_OFF 20992          // [16][68]  = 1088
#define A1_OFF 22080          // [128][68] = 8704 (im2col K-chunk)
#define A2_OFF 30784          // [128][68] = 8704 (hidden acts)
#define SX_OFF 39488          // [3][12][40] = 1440
#define KT_OFF 40928          // 256 ints
#define SMEM_FLOATS 41184     // 164,736 bytes

// ---------------- scratch ----------------
__device__ float g_y[9 * B2 * HP * HP];

// ---------------- helpers ----------------
static __device__ __forceinline__ uint32_t f2tf32(float v) {
    uint32_t r;
    asm("cvt.rn.tf32.f32 %0, %1;" : "=r"(r) : "f"(v));
    return r;
}

// D += A(16x8,row) * B(8x8,col); tf32 operands, f32 accum.
#define MMA8(c, a0, a1, a2, a3, b0, b1)                                  \
    asm volatile("mma.sync.aligned.m16n8k8.row.col.f32.tf32.tf32.f32 "   \
        "{%0,%1,%2,%3}, {%4,%5,%6,%7}, {%8,%9}, {%0,%1,%2,%3};"          \
        : "+f"((c)[0]), "+f"((c)[1]), "+f"((c)[2]), "+f"((c)[3])         \
        : "r"(a0), "r"(a1), "r"(a2), "r"(a3), "r"(b0), "r"(b1))

__global__ __launch_bounds__(NTHR, 1) void mlp_kernel(
    const float* __restrict__ x,
    const float* __restrict__ W1, const float* __restrict__ b1,
    const float* __restrict__ W2, const float* __restrict__ b2,
    const float* __restrict__ W3, const float* __restrict__ b3)
{
    extern __shared__ float smem[];
    uint32_t* su = (uint32_t*)smem;
    const int tid  = threadIdx.x;
    const int lane = tid & 31;
    const int warp = tid >> 5;          // 0..7, owns rows 16w..16w+15
    const int g    = lane >> 2;         // groupID
    const int tig  = lane & 3;          // threadID_in_group

    // ---- weights -> smem, tf32-rounded, [n][K] row-major, bias folded ----
    for (int idx = tid; idx < N12 * K1; idx += NTHR) {
        int n = idx >> 8, k = idx & 255;
        float v = 0.f;
        if (n < 50) { if (k < 243) v = W1[n * 243 + k]; else if (k == 243) v = b1[n]; }
        su[W1_OFF + n * STRW1 + k] = f2tf32(v);
    }
    for (int idx = tid; idx < N12 * K2; idx += NTHR) {
        int n = idx >> 6, k = idx & 63;
        float v = 0.f;
        if (n < 50) { if (k < 50) v = W2[n * 50 + k]; else if (k == 50) v = b2[n]; }
        su[W2_OFF + n * STR + k] = f2tf32(v);
    }
    for (int idx = tid; idx < N3 * K2; idx += NTHR) {
        int n = idx >> 6, k = idx & 63;
        float v = 0.f;
        if (n < 9) { if (k < 50) v = W3[n * 50 + k]; else if (k == 50) v = b3[n]; }
        su[W3_OFF + n * STR + k] = f2tf32(v);
    }
    int* ktab = (int*)(smem + KT_OFF);
    for (int k = tid; k < 256; k += NTHR) {
        int v;
        if (k < 243) { int c = k / 81, rm = k % 81; v = (c * SXH + rm / 9) * SXW + (rm % 9); }
        else v = (k == 243) ? -1 : -2;
        ktab[k] = v;
    }

    for (int t = blockIdx.x; t < NTILES; t += gridDim.x) {
        const int b  = t / (YG * XG);
        const int rm = t % (YG * XG);
        const int py0 = (rm / XG) * TROWS;
        const int px0 = (rm % XG) * TCOLS;

        __syncthreads();   // prev tile's readers of sX / sA2 are done

        // ---- input tile -> smem ----
        const float* xb = x + (size_t)b * (C_IN * H_IN * W_IN);
        for (int i = tid; i < C_IN * SXH * SXW; i += NTHR) {
            int q = i % SXW;
            int rr = (i / SXW) % SXH;
            int c = i / (SXH * SXW);
            int gxx = px0 + q;
            smem[SX_OFF + i] = (gxx < W_IN) ? xb[(c * H_IN + (py0 + rr)) * W_IN + gxx] : 0.f;
        }

        // ================= layer 1: K=256 in 4 chunks of 64 =================
        float c1[8][4];
        #pragma unroll
        for (int j = 0; j < 8; j++)
            #pragma unroll
            for (int d = 0; d < 4; d++) c1[j][d] = 0.f;

        for (int ch = 0; ch < 4; ch++) {
            __syncthreads();   // prior chunk consumed (ch=0: sX stores visible)
            // im2col chunk build: A[128][64] tf32
            #pragma unroll 4
            for (int e = 0; e < 32; e++) {
                int idx = e * NTHR + tid;
                int m = idx >> 6, kk = idx & 63;
                int off = ktab[ch * 64 + kk];
                float v = (off >= 0)
                    ? smem[SX_OFF + off + (m >> 5) * SXW + (m & 31)]
                    : ((off == -1) ? 1.f : 0.f);
                su[A1_OFF + m * STR + kk] = f2tf32(v);
            }
            __syncthreads();

            const uint32_t* Ab = su + A1_OFF + (warp * 16 + g) * STR;
            for (int ks = 0; ks < 8; ks++) {
                const int k0 = ks * 8;
                uint32_t a0 = Ab[k0 + tig];
                uint32_t a1 = Ab[8 * STR + k0 + tig];
                uint32_t a2 = Ab[k0 + tig + 4];
                uint32_t a3 = Ab[8 * STR + k0 + tig + 4];
                const int kg = ch * 64 + k0;
                #pragma unroll
                for (int j = 0; j < 8; j++) {
                    const uint32_t* Bb = su + W1_OFF + (j * 8 + g) * STRW1 + kg;
                    MMA8(c1[j], a0, a1, a2, a3, Bb[tig], Bb[tig + 4]);
                }
            }
        }

        // ---- epilogue 1: relu + tf32 -> sA2 (bias col 50 = 1) ----
        #pragma unroll
        for (int j = 0; j < 8; j++) {
            #pragma unroll
            for (int d = 0; d < 4; d++) {
                int row = g + ((d >= 2) ? 8 : 0);
                int n = j * 8 + 2 * tig + (d & 1);
                float v = fmaxf(c1[j][d], 0.f);
                if (n == 50) v = 1.f; else if (n > 50) v = 0.f;
                su[A2_OFF + (warp * 16 + row) * STR + n] = f2tf32(v);
            }
        }
        __syncthreads();

        // ================= layer 2: K=64 =================
        float c2[8][4];
        #pragma unroll
        for (int j = 0; j < 8; j++)
            #pragma unroll
            for (int d = 0; d < 4; d++) c2[j][d] = 0.f;
        {
            const uint32_t* Ab = su + A2_OFF + (warp * 16 + g) * STR;
            for (int ks = 0; ks < 8; ks++) {
                const int k0 = ks * 8;
                uint32_t a0 = Ab[k0 + tig];
                uint32_t a1 = Ab[8 * STR + k0 + tig];
                uint32_t a2 = Ab[k0 + tig + 4];
                uint32_t a3 = Ab[8 * STR + k0 + tig + 4];
                #pragma unroll
                for (int j = 0; j < 8; j++) {
                    const uint32_t* Bb = su + W2_OFF + (j * 8 + g) * STR + k0;
                    MMA8(c2[j], a0, a1, a2, a3, Bb[tig], Bb[tig + 4]);
                }
            }
        }
        __syncthreads();   // all warps done reading sA2 (h1)

        // ---- epilogue 2: relu + tf32 -> sA2 (h2, bias col 50 = 1) ----
        #pragma unroll
        for (int j = 0; j < 8; j++) {
            #pragma unroll
            for (int d = 0; d < 4; d++) {
                int row = g + ((d >= 2) ? 8 : 0);
                int n = j * 8 + 2 * tig + (d & 1);
                float v = fmaxf(c2[j][d], 0.f);
                if (n == 50) v = 1.f; else if (n > 50) v = 0.f;
                su[A2_OFF + (warp * 16 + row) * STR + n] = f2tf32(v);
            }
        }
        __syncthreads();

        // ================= layer 3: K=64, N=16 =================
        float c3[2][4];
        #pragma unroll
        for (int j = 0; j < 2; j++)
            #pragma unroll
            for (int d = 0; d < 4; d++) c3[j][d] = 0.f;
        {
            const uint32_t* Ab = su + A2_OFF + (warp * 16 + g) * STR;
            for (int ks = 0; ks < 8; ks++) {
                const int k0 = ks * 8;
                uint32_t a0 = Ab[k0 + tig];
                uint32_t a1 = Ab[8 * STR + k0 + tig];
                uint32_t a2 = Ab[k0 + tig + 4];
                uint32_t a3 = Ab[8 * STR + k0 + tig + 4];
                #pragma unroll
                for (int j = 0; j < 2; j++) {
                    const uint32_t* Bb = su + W3_OFF + (j * 8 + g) * STR + k0;
                    MMA8(c3[j], a0, a1, a2, a3, Bb[tig], Bb[tig + 4]);
                }
            }
        }

        // ---- epilogue 3: write y to g_y ----
        #pragma unroll
        for (int j = 0; j < 2; j++) {
            #pragma unroll
            for (int d = 0; d < 4; d++) {
                int row = g + ((d >= 2) ? 8 : 0);
                int n = j * 8 + 2 * tig + (d & 1);
                int m = warp * 16 + row;
                int py = py0 + (m >> 5);
                int px = px0 + (m & 31);
                if (n < 9 && px < HP)
                    g_y[(((size_t)n * B2 + b) * HP + py) * HP + px] = c3[j][d];
            }
        }
    }
}

// ---- fold (overlap-add + divisor) as pure gather ----
__global__ __launch_bounds__(256) void fold_kernel(float* __restrict__ out)
{
    int idx = blockIdx.x * blockDim.x + threadIdx.x;
    const int total = B2 * OUT_H * OUT_H;
    if (idx >= total) return;
    int oj = idx % OUT_H;
    int t  = idx / OUT_H;
    int oi = t % OUT_H;
    int b  = t / OUT_H;

    float acc = 0.f;
    int cnt = 0;
    #pragma unroll
    for (int di = 0; di < KO; di++) {
        int pi = oi - di;
        if (pi < 0 || pi >= HP) continue;
        #pragma unroll
        for (int dj = 0; dj < KO; dj++) {
            int pj = oj - dj;
            if (pj < 0 || pj >= HP) continue;
            acc += g_y[((di * KO + dj) * B2 + b) * (HP * HP) + pi * HP + pj];
            cnt++;
        }
    }
    out[idx] = acc / (float)cnt;
}

extern "C" void kernel_launch(void* const* d_in, const int* in_sizes, int n_in,
                              void* d_out, int out_size)
{
    const float* x  = (const float*)d_in[0];
    const float* W1 = (const float*)d_in[1];
    const float* b1 = (const float*)d_in[2];
    const float* W2 = (const float*)d_in[3];
    const float* b2 = (const float*)d_in[4];
    const float* W3 = (const float*)d_in[5];
    const float* b3 = (const float*)d_in[6];
    float* out = (float*)d_out;

    const int smem_bytes = SMEM_FLOATS * 4;   // 164,736 B
    cudaFuncSetAttribute(mlp_kernel,
                         cudaFuncAttributeMaxDynamicSharedMemorySize, smem_bytes);

    mlp_kernel<<<NCTA, NTHR, smem_bytes>>>(x, W1, b1, W2, b2, W3, b3);

    const int total = B2 * OUT_H * OUT_H;
    fold_kernel<<<(total + 255) / 256, 256>>>(out);
}

// round 9
// speedup vs baseline: 3.0633x; 2.2453x over previous
#include <cuda_runtime.h>
#include <cstdint>

// ---------------- problem constants ----------------
#define KI     9
#define KO     3
#define C_IN   3
#define H_IN   192
#define W_IN   192
#define B2     16
#define HP     184            // H - KI + 1
#define OUT_H  186

// ---------------- tiling ----------------
#define TROWS  8
#define TCOLS  32
#define MROWS  256            // rows (positions) per tile
#define YG     23             // 184/8
#define XG     6              // ceil(184/32)
#define NTILES (B2*YG*XG)     // 2208
#define NTHR   512
#define NCTA   148

#define SXH    16             // TROWS + 8
#define SXW    40             // TCOLS + 8

// ---------------- smem layout (float offsets) ----------------
#define W1F_OFF 0             // [32ks][4jp][32lane][4] = 16384
#define W2F_OFF 16384         // [8ks][4jp][32][4]      = 4096
#define W3F_OFF 20480         // [8ks][1jp][32][4]      = 1024
#define A2F_OFF 21504         // [8ks][512tid][4]       = 16384
#define SX_OFF  37888         // [3][16][40]            = 1920
#define KT_OFF  39808         // 256 ints
#define SB1_OFF 40064         // 64
#define SB2_OFF 40128         // 64
#define SB3_OFF 40192         // 16
#define SMEM_FLOATS 40208     // 160,832 bytes

// ---------------- scratch ----------------
__device__ float g_y[9 * B2 * HP * HP];

static __device__ __forceinline__ uint32_t f2tf32(float v) {
    uint32_t r;
    asm("cvt.rn.tf32.f32 %0, %1;" : "=r"(r) : "f"(v));
    return r;
}

// D += A(16x8,row) * B(8x8,col); tf32 operands, f32 accum.
#define MMA8(c, a0, a1, a2, a3, b0, b1)                                  \
    asm volatile("mma.sync.aligned.m16n8k8.row.col.f32.tf32.tf32.f32 "   \
        "{%0,%1,%2,%3}, {%4,%5,%6,%7}, {%8,%9}, {%0,%1,%2,%3};"          \
        : "+f"((c)[0]), "+f"((c)[1]), "+f"((c)[2]), "+f"((c)[3])         \
        : "r"(a0), "r"(a1), "r"(a2), "r"(a3), "r"(b0), "r"(b1))

#define LDS128U(r0, r1, r2, r3, addr)                                    \
    asm volatile("ld.shared.v4.b32 {%0,%1,%2,%3}, [%4];"                 \
        : "=r"(r0), "=r"(r1), "=r"(r2), "=r"(r3) : "r"(addr))

static __device__ __forceinline__ uint32_t smem_u32(const void* p) {
    uint32_t a;
    asm("{ .reg .u64 t; cvta.to.shared.u64 t, %1; cvt.u32.u64 %0, t; }" : "=r"(a) : "l"(p));
    return a;
}

__global__ __launch_bounds__(NTHR, 1) void mlp_kernel(
    const float* __restrict__ x,
    const float* __restrict__ W1, const float* __restrict__ b1,
    const float* __restrict__ W2, const float* __restrict__ b2,
    const float* __restrict__ W3, const float* __restrict__ b3)
{
    extern __shared__ float smem[];
    uint32_t* su = (uint32_t*)smem;
    const uint32_t sbase = smem_u32(smem);
    const int tid  = threadIdx.x;
    const int lane = tid & 31;
    const int warp = tid >> 5;          // 0..15, owns rows 16w..16w+15
    const int g    = lane >> 2;
    const int tig  = lane & 3;

    // ---------------- one-time prepack ----------------
    // W1 fragment-major: [ks][jp][lane][slot]; slot: {j=2jp:b0,b1, j=2jp+1:b0,b1}
    for (int idx = tid; idx < 16384; idx += NTHR) {
        int slot = idx & 3, ln = (idx >> 2) & 31, jp = (idx >> 7) & 3, ks = idx >> 9;
        int gg = ln >> 2, tt = ln & 3;
        int j = 2 * jp + (slot >> 1);
        int kk = ks * 8 + tt + ((slot & 1) ? 4 : 0);
        int n = j * 8 + gg;
        float v = (n < 50 && kk < 243) ? W1[n * 243 + kk] : 0.f;
        su[W1F_OFF + idx] = f2tf32(v);
    }
    for (int idx = tid; idx < 4096; idx += NTHR) {
        int slot = idx & 3, ln = (idx >> 2) & 31, jp = (idx >> 7) & 3, ks = idx >> 9;
        int gg = ln >> 2, tt = ln & 3;
        int j = 2 * jp + (slot >> 1);
        int kk = ks * 8 + tt + ((slot & 1) ? 4 : 0);
        int n = j * 8 + gg;
        float v = (n < 50 && kk < 50) ? W2[n * 50 + kk] : 0.f;
        su[W2F_OFF + idx] = f2tf32(v);
    }
    for (int idx = tid; idx < 1024; idx += NTHR) {
        int slot = idx & 3, ln = (idx >> 2) & 31, ks = idx >> 7;
        int gg = ln >> 2, tt = ln & 3;
        int j = slot >> 1;
        int kk = ks * 8 + tt + ((slot & 1) ? 4 : 0);
        int n = j * 8 + gg;
        float v = (n < 9 && kk < 50) ? W3[n * 50 + kk] : 0.f;
        su[W3F_OFF + idx] = f2tf32(v);
    }
    {
        int* ktab = (int*)(smem + KT_OFF);
        for (int k = tid; k < 256; k += NTHR) {
            int v = 0;
            if (k < 243) { int c = k / 81, rm = k % 81; v = (c * SXH + rm / 9) * SXW + (rm % 9); }
            ktab[k] = v;
        }
        for (int n = tid; n < 64; n += NTHR) {
            smem[SB1_OFF + n] = (n < 50) ? b1[n] : 0.f;
            smem[SB2_OFF + n] = (n < 50) ? b2[n] : 0.f;
        }
        for (int n = tid; n < 16; n += NTHR) smem[SB3_OFF + n] = (n < 9) ? b3[n] : 0.f;
    }
    __syncthreads();

    const int* ktab = (const int*)(smem + KT_OFF);
    const int rowA = warp * 16 + g;
    const int rowB = rowA + 8;
    // sx per-row base offsets (row -> (py,px) -> smem offset)
    const int srowA = (rowA >> 5) * SXW + (rowA & 31);
    const int srowB = (rowB >> 5) * SXW + (rowB & 31);
    const uint32_t wbase1 = sbase + W1F_OFF * 4 + lane * 16;
    const uint32_t wbase2 = sbase + W2F_OFF * 4 + lane * 16;
    const uint32_t wbase3 = sbase + W3F_OFF * 4 + lane * 16;
    const uint32_t abase2 = sbase + A2F_OFF * 4 + tid * 16;

    // epilogue target addressing for value (row-half ai, j, n)
    const int t01 = 2 * tig;    // n = j*8 + t01 + (d&1)

    for (int t = blockIdx.x; t < NTILES; t += NCTA) {
        const int b  = t / (YG * XG);
        const int rm = t % (YG * XG);
        const int py0 = (rm / XG) * TROWS;
        const int px0 = (rm % XG) * TCOLS;

        __syncthreads();   // everyone done with previous sx
        const float* xb = x + (size_t)b * (C_IN * H_IN * W_IN);
        for (int i = tid; i < C_IN * SXH * SXW; i += NTHR) {
            int q = i % SXW;
            int rr = (i / SXW) % SXH;
            int c = i / (SXH * SXW);
            int gxx = px0 + q;
            smem[SX_OFF + i] = (gxx < W_IN) ? xb[(c * H_IN + (py0 + rr)) * W_IN + gxx] : 0.f;
        }
        __syncthreads();

        const float* sxA = smem + SX_OFF + srowA;
        const float* sxB = smem + SX_OFF + srowB;

        // ================= layer 1: K=243 (30 full ksteps + 1 partial) ========
        float c1[8][4];
        #pragma unroll
        for (int j = 0; j < 8; j++) {
            float bv0 = smem[SB1_OFF + j * 8 + t01];
            float bv1 = smem[SB1_OFF + j * 8 + t01 + 1];
            c1[j][0] = bv0; c1[j][1] = bv1; c1[j][2] = bv0; c1[j][3] = bv1;
        }
        #pragma unroll
        for (int ks = 0; ks < 30; ks++) {
            int ka = ktab[ks * 8 + tig];
            int kb = ktab[ks * 8 + tig + 4];
            uint32_t a0 = f2tf32(sxA[ka]);
            uint32_t a1 = f2tf32(sxB[ka]);
            uint32_t a2 = f2tf32(sxA[kb]);
            uint32_t a3 = f2tf32(sxB[kb]);
            #pragma unroll
            for (int jp = 0; jp < 4; jp++) {
                uint32_t b0, b1r, b2r, b3r;
                LDS128U(b0, b1r, b2r, b3r, wbase1 + (ks * 4 + jp) * 512);
                MMA8(c1[2 * jp],     a0, a1, a2, a3, b0,  b1r);
                MMA8(c1[2 * jp + 1], a0, a1, a2, a3, b2r, b3r);
            }
        }
        {   // ks = 30: k = 240..242 live in a0/a1 (tig<3); a2/a3 all zero-weight
            int ka = ktab[240 + tig];
            uint32_t a0 = 0, a1 = 0;
            if (tig < 3) { a0 = f2tf32(sxA[ka]); a1 = f2tf32(sxB[ka]); }
            #pragma unroll
            for (int jp = 0; jp < 4; jp++) {
                uint32_t b0, b1r, b2r, b3r;
                LDS128U(b0, b1r, b2r, b3r, wbase1 + (30 * 4 + jp) * 512);
                MMA8(c1[2 * jp],     a0, a1, 0u, 0u, b0,  b1r);
                MMA8(c1[2 * jp + 1], a0, a1, 0u, 0u, b2r, b3r);
            }
        }

        // ---- epilogue 1: relu -> tf32 -> A2F fragment-major (n>=50 -> 0) ----
        #pragma unroll
        for (int j = 0; j < 8; j++) {
            #pragma unroll
            for (int d = 0; d < 4; d++) {
                int nr = t01 + (d & 1);             // n - j*8, 0..7
                int n = j * 8 + nr;
                float v = (n < 50) ? fmaxf(c1[j][d], 0.f) : 0.f;
                int slot = ((d >= 2) ? 1 : 0) + 2 * (nr >> 2);
                uint32_t ad = sbase + (A2F_OFF + (j * NTHR + warp * 32 + g * 4 + (nr & 3)) * 4 + slot) * 4;
                uint32_t uv = f2tf32(v);
                asm volatile("st.shared.b32 [%0], %1;" :: "r"(ad), "r"(uv) : "memory");
            }
        }
        __syncwarp();

        // ================= layer 2: K=50 (7 ksteps; ks=6 zero-padded) =========
        float c2[8][4];
        #pragma unroll
        for (int j = 0; j < 8; j++) {
            float bv0 = smem[SB2_OFF + j * 8 + t01];
            float bv1 = smem[SB2_OFF + j * 8 + t01 + 1];
            c2[j][0] = bv0; c2[j][1] = bv1; c2[j][2] = bv0; c2[j][3] = bv1;
        }
        #pragma unroll
        for (int ks = 0; ks < 7; ks++) {
            uint32_t a0, a1, a2, a3;
            LDS128U(a0, a1, a2, a3, abase2 + ks * (NTHR * 16));
            #pragma unroll
            for (int jp = 0; jp < 4; jp++) {
                uint32_t b0, b1r, b2r, b3r;
                LDS128U(b0, b1r, b2r, b3r, wbase2 + (ks * 4 + jp) * 512);
                MMA8(c2[2 * jp],     a0, a1, a2, a3, b0,  b1r);
                MMA8(c2[2 * jp + 1], a0, a1, a2, a3, b2r, b3r);
            }
        }
        __syncwarp();

        // ---- epilogue 2: h2 -> A2F ----
        #pragma unroll
        for (int j = 0; j < 8; j++) {
            #pragma unroll
            for (int d = 0; d < 4; d++) {
                int nr = t01 + (d & 1);
                int n = j * 8 + nr;
                float v = (n < 50) ? fmaxf(c2[j][d], 0.f) : 0.f;
                int slot = ((d >= 2) ? 1 : 0) + 2 * (nr >> 2);
                uint32_t ad = sbase + (A2F_OFF + (j * NTHR + warp * 32 + g * 4 + (nr & 3)) * 4 + slot) * 4;
                uint32_t uv = f2tf32(v);
                asm volatile("st.shared.b32 [%0], %1;" :: "r"(ad), "r"(uv) : "memory");
            }
        }
        __syncwarp();

        // ================= layer 3: K=50, N=16 =================
        float c3[2][4];
        #pragma unroll
        for (int j = 0; j < 2; j++) {
            float bv0 = smem[SB3_OFF + j * 8 + t01];
            float bv1 = smem[SB3_OFF + j * 8 + t01 + 1];
            c3[j][0] = bv0; c3[j][1] = bv1; c3[j][2] = bv0; c3[j][3] = bv1;
        }
        #pragma unroll
        for (int ks = 0; ks < 7; ks++) {
            uint32_t a0, a1, a2, a3;
            LDS128U(a0, a1, a2, a3, abase2 + ks * (NTHR * 16));
            uint32_t b0, b1r, b2r, b3r;
            LDS128U(b0, b1r, b2r, b3r, wbase3 + ks * 512);
            MMA8(c3[0], a0, a1, a2, a3, b0,  b1r);
            MMA8(c3[1], a0, a1, a2, a3, b2r, b3r);
        }

        // ---- epilogue 3: y -> g_y ----
        #pragma unroll
        for (int j = 0; j < 2; j++) {
            #pragma unroll
            for (int d = 0; d < 4; d++) {
                int n = j * 8 + t01 + (d & 1);
                if (n < 9) {
                    int row = (d >= 2) ? rowB : rowA;
                    int py = py0 + (row >> 5);
                    int px = px0 + (row & 31);
                    if (px < HP)
                        g_y[(((size_t)n * B2 + b) * HP + py) * HP + px] = c3[j][d];
                }
            }
        }
    }
}

// ---- fold (overlap-add + divisor) as pure gather ----
__global__ __launch_bounds__(256) void fold_kernel(float* __restrict__ out)
{
    int idx = blockIdx.x * blockDim.x + threadIdx.x;
    const int total = B2 * OUT_H * OUT_H;
    if (idx >= total) return;
    int oj = idx % OUT_H;
    int t  = idx / OUT_H;
    int oi = t % OUT_H;
    int b  = t / OUT_H;

    float acc = 0.f;
    int cnt = 0;
    #pragma unroll
    for (int di = 0; di < KO; di++) {
        int pi = oi - di;
        if (pi < 0 || pi >= HP) continue;
        #pragma unroll
        for (int dj = 0; dj < KO; dj++) {
            int pj = oj - dj;
            if (pj < 0 || pj >= HP) continue;
            acc += g_y[((di * KO + dj) * B2 + b) * (HP * HP) + pi * HP + pj];
            cnt++;
        }
    }
    out[idx] = acc / (float)cnt;
}

extern "C" void kernel_launch(void* const* d_in, const int* in_sizes, int n_in,
                              void* d_out, int out_size)
{
    const float* x  = (const float*)d_in[0];
    const float* W1 = (const float*)d_in[1];
    const float* b1 = (const float*)d_in[2];
    const float* W2 = (const float*)d_in[3];
    const float* b2 = (const float*)d_in[4];
    const float* W3 = (const float*)d_in[5];
    const float* b3 = (const float*)d_in[6];
    float* out = (float*)d_out;

    const int smem_bytes = SMEM_FLOATS * 4;   // 160,832 B
    cudaFuncSetAttribute(mlp_kernel,
                         cudaFuncAttributeMaxDynamicSharedMemorySize, smem_bytes);

    mlp_kernel<<<NCTA, NTHR, smem_bytes>>>(x, W1, b1, W2, b2, W3, b3);

    const int total = B2 * OUT_H * OUT_H;
    fold_kernel<<<(total + 255) / 256, 256>>>(out);
}